// round 2
// baseline (speedup 1.0000x reference)
#include <cuda_runtime.h>
#include <cstdint>

#define Bn 16
#define Tn 512
#define En 2048
#define Hn 1024
#define Dn 128

// ---------------- scratch (device globals; no allocs allowed) ----------------
__device__ float        g_xw[(size_t)Bn * Tn * Hn];   // 32 MB: precomputed x@W_ih^T + biases
__device__ float        g_h[2][Hn];                   // double-buffered hidden state
__device__ float        g_hs[Bn * Hn];                // per-batch final hidden
__device__ unsigned int g_ctr;                        // grid barrier counter

// ---------------- init: must reset per launch (graph replays) ----------------
__global__ void init_kernel() {
    int tid = blockIdx.x * blockDim.x + threadIdx.x;
    if (tid < 2 * Hn) ((float*)g_h)[tid] = 0.0f;
    if (tid == 0) g_ctr = 0u;
}

// ---------------- xW GEMM: C[8192,1024] = X[8192,2048] @ W_ih^T + (b_ih+b_hh) -
#define BM 128
#define BN 128
#define BK 16
#define SP 132   // padded smem row stride (floats): 528B rows, 16B-aligned, kills 4-way STS conflicts

__global__ __launch_bounds__(256, 2) void xw_gemm(
    const float* __restrict__ X, const float* __restrict__ Wih,
    const float* __restrict__ bih, const float* __restrict__ bhh,
    const int* __restrict__ lengths)
{
    const int m0 = blockIdx.x * BM;
    const int n0 = blockIdx.y * BN;
    const int b  = m0 / Tn;         // BM=128 divides Tn=512: tile stays inside one batch row
    const int t0 = m0 % Tn;
    if (t0 >= lengths[b]) return;   // fully-padded tile: its xw is never read

    __shared__ __align__(16) float As[BK * SP];
    __shared__ __align__(16) float Bs[BK * SP];

    const int tid = threadIdx.x;
    const int tx = tid & 15;
    const int ty = tid >> 4;

    float acc[8][8];
#pragma unroll
    for (int i = 0; i < 8; i++)
#pragma unroll
        for (int j = 0; j < 8; j++) acc[i][j] = 0.0f;

    for (int k0 = 0; k0 < En; k0 += BK) {
#pragma unroll
        for (int i = 0; i < 2; i++) {
            int idx = tid + i * 256;            // 0..511 float4s per tile
            int m   = idx >> 2;                 // 0..127
            int kq  = (idx & 3) << 2;           // 0,4,8,12
            float4 av = *(const float4*)&X  [(size_t)(m0 + m) * En + k0 + kq];
            float4 bv = *(const float4*)&Wih[(size_t)(n0 + m) * En + k0 + kq];
            As[(kq + 0) * SP + m] = av.x; As[(kq + 1) * SP + m] = av.y;
            As[(kq + 2) * SP + m] = av.z; As[(kq + 3) * SP + m] = av.w;
            Bs[(kq + 0) * SP + m] = bv.x; Bs[(kq + 1) * SP + m] = bv.y;
            Bs[(kq + 2) * SP + m] = bv.z; Bs[(kq + 3) * SP + m] = bv.w;
        }
        __syncthreads();
#pragma unroll
        for (int k = 0; k < BK; k++) {
            float4 a0 = *(const float4*)&As[k * SP + 4 * ty];
            float4 a1 = *(const float4*)&As[k * SP + 64 + 4 * ty];
            float4 b0 = *(const float4*)&Bs[k * SP + 4 * tx];
            float4 b1 = *(const float4*)&Bs[k * SP + 64 + 4 * tx];
            float ar[8] = {a0.x, a0.y, a0.z, a0.w, a1.x, a1.y, a1.z, a1.w};
            float br[8] = {b0.x, b0.y, b0.z, b0.w, b1.x, b1.y, b1.z, b1.w};
#pragma unroll
            for (int i = 0; i < 8; i++)
#pragma unroll
                for (int j = 0; j < 8; j++)
                    acc[i][j] = fmaf(ar[i], br[j], acc[i][j]);
        }
        __syncthreads();
    }

    // epilogue: + (b_ih + b_hh)
    float4 bi0 = *(const float4*)&bih[n0 + 4 * tx];
    float4 bh0 = *(const float4*)&bhh[n0 + 4 * tx];
    float4 bi1 = *(const float4*)&bih[n0 + 64 + 4 * tx];
    float4 bh1 = *(const float4*)&bhh[n0 + 64 + 4 * tx];
    float4 c0 = make_float4(bi0.x + bh0.x, bi0.y + bh0.y, bi0.z + bh0.z, bi0.w + bh0.w);
    float4 c1 = make_float4(bi1.x + bh1.x, bi1.y + bh1.y, bi1.z + bh1.z, bi1.w + bh1.w);
#pragma unroll
    for (int i = 0; i < 8; i++) {
        int m = m0 + ((i < 4) ? (4 * ty + i) : (64 + 4 * ty + i - 4));
        float4 o0 = make_float4(acc[i][0] + c0.x, acc[i][1] + c0.y,
                                acc[i][2] + c0.z, acc[i][3] + c0.w);
        float4 o1 = make_float4(acc[i][4] + c1.x, acc[i][5] + c1.y,
                                acc[i][6] + c1.z, acc[i][7] + c1.w);
        *(float4*)&g_xw[(size_t)m * Hn + n0 + 4 * tx]      = o0;
        *(float4*)&g_xw[(size_t)m * Hn + n0 + 64 + 4 * tx] = o1;
    }
}

// ---------------- sequential recurrence: persistent grid, 1 barrier/step ------
#define NBLK 128   // CTAs; 1 per SM, all co-resident (128 < 148)
#define RPC  8     // rows of W_hh per CTA (128*8 = 1024)

__global__ __launch_bounds__(128, 1) void rnn_kernel(
    const float* __restrict__ Whh, const int* __restrict__ lengths)
{
    __shared__ __align__(16) float4 Ws4[RPC * (Hn / 4)];  // 32 KB: this CTA's 8 rows of W_hh
    __shared__ __align__(16) float4 hsh[Hn / 4];          // 4 KB: staged h

    const int tid  = threadIdx.x;
    const int cta  = blockIdx.x;
    const int w    = tid >> 5;
    const int lane = tid & 31;

    // load weight slice once
    const float4* src4 = (const float4*)Whh + (size_t)cta * RPC * (Hn / 4);
#pragma unroll
    for (int i = 0; i < (RPC * Hn / 4) / 128; i++)
        Ws4[tid + i * 128] = src4[tid + i * 128];
    __syncthreads();

    const int r0  = 2 * w;
    const int r1  = 2 * w + 1;
    const int gr0 = cta * RPC + r0;
    const int gr1 = cta * RPC + r1;

    unsigned int step = 0;
    for (int b = 0; b < Bn; b++) {
        const int L = __ldg(&lengths[b]);
        const float* xwb = g_xw + (size_t)b * Tn * Hn;
        for (int t = 0; t < L; t++) {
            const float* hread  = g_h[step & 1u];
            float*       hwrite = g_h[(step & 1u) ^ 1u];

            // prefetch this step's xw values early (used ~400cyc later)
            float xw0 = 0.0f, xw1 = 0.0f;
            if (lane == 0) {
                xw0 = __ldcg(&xwb[(size_t)t * Hn + gr0]);
                xw1 = __ldcg(&xwb[(size_t)t * Hn + gr1]);
            }

            // stage h (L2-only loads: written by other SMs last step)
            const float4* hr4 = (const float4*)hread;
            float4 h0 = __ldcg(&hr4[tid]);
            float4 h1 = __ldcg(&hr4[tid + 128]);
            hsh[tid]       = h0;
            hsh[tid + 128] = h1;
            __syncthreads();

            // warp w computes rows r0, r1 (dual accumulators per row to shorten FMA chain)
            float a0 = 0.f, a1 = 0.f, a2 = 0.f, a3 = 0.f;
#pragma unroll
            for (int i = 0; i < 8; i++) {
                float4 hv = hsh[lane + (i << 5)];
                float4 w0 = Ws4[r0 * 256 + lane + (i << 5)];
                float4 w1 = Ws4[r1 * 256 + lane + (i << 5)];
                if (i & 1) {
                    a2 = fmaf(hv.w, w0.w, fmaf(hv.z, w0.z, fmaf(hv.y, w0.y, fmaf(hv.x, w0.x, a2))));
                    a3 = fmaf(hv.w, w1.w, fmaf(hv.z, w1.z, fmaf(hv.y, w1.y, fmaf(hv.x, w1.x, a3))));
                } else {
                    a0 = fmaf(hv.w, w0.w, fmaf(hv.z, w0.z, fmaf(hv.y, w0.y, fmaf(hv.x, w0.x, a0))));
                    a1 = fmaf(hv.w, w1.w, fmaf(hv.z, w1.z, fmaf(hv.y, w1.y, fmaf(hv.x, w1.x, a1))));
                }
            }
            float accA = a0 + a2;
            float accB = a1 + a3;
#pragma unroll
            for (int off = 16; off > 0; off >>= 1) {
                accA += __shfl_xor_sync(0xffffffffu, accA, off);
                accB += __shfl_xor_sync(0xffffffffu, accB, off);
            }

            if (lane == 0) {
                float hn0 = tanhf(xw0 + accA);
                float hn1 = tanhf(xw1 + accB);
                __stcg(&hwrite[gr0], hn0);
                __stcg(&hwrite[gr1], hn1);
                if (t == L - 1) {
                    __stcg(&g_hs[b * Hn + gr0], hn0);
                    __stcg(&g_hs[b * Hn + gr1], hn1);
                }
                __threadfence();   // release our slice before arriving
            }
            __syncthreads();

            // grid barrier: arrival implies (read h done + wrote slice), so
            // double-buffering with ONE barrier per step is race-free.
            if (tid == 0) {
                atomicAdd(&g_ctr, 1u);
                const unsigned int target = (step + 1u) * NBLK;
                unsigned int v;
                do {
                    asm volatile("ld.acquire.gpu.global.u32 %0, [%1];"
                                 : "=r"(v) : "l"(&g_ctr) : "memory");
                } while (v < target);
            }
            __syncthreads();
            step++;
        }
    }
}

// ---------------- head: out[16,128] = hs @ W_l1^T + b_l1 ----------------------
__global__ void head_kernel(const float* __restrict__ Wl1,
                            const float* __restrict__ bl1,
                            float* __restrict__ out)
{
    const int b = blockIdx.x;
    const int d = threadIdx.x;   // 128
    __shared__ float hsh[Hn];
    for (int i = d; i < Hn; i += Dn) hsh[i] = g_hs[b * Hn + i];
    __syncthreads();

    float acc = bl1[d];
    const float* wr = Wl1 + (size_t)d * Hn;
#pragma unroll 4
    for (int k = 0; k < Hn; k += 4) {
        float4 wv = *(const float4*)&wr[k];
        acc = fmaf(wv.x, hsh[k + 0], acc);
        acc = fmaf(wv.y, hsh[k + 1], acc);
        acc = fmaf(wv.z, hsh[k + 2], acc);
        acc = fmaf(wv.w, hsh[k + 3], acc);
    }
    out[b * Dn + d] = acc;
}

// ---------------- launch ------------------------------------------------------
extern "C" void kernel_launch(void* const* d_in, const int* in_sizes, int n_in,
                              void* d_out, int out_size)
{
    const float* x       = (const float*)d_in[0];
    const int*   lengths = (const int*)  d_in[1];
    const float* W_ih    = (const float*)d_in[2];
    const float* W_hh    = (const float*)d_in[3];
    const float* b_ih    = (const float*)d_in[4];
    const float* b_hh    = (const float*)d_in[5];
    const float* W_l1    = (const float*)d_in[6];
    const float* b_l1    = (const float*)d_in[7];
    float* out = (float*)d_out;

    init_kernel<<<8, 256>>>();

    dim3 grid(Bn * Tn / BM, Hn / BN);
    xw_gemm<<<grid, 256>>>(x, W_ih, b_ih, b_hh, lengths);

    rnn_kernel<<<NBLK, 128>>>(W_hh, lengths);

    head_kernel<<<Bn, Dn>>>(W_l1, b_l1, out);
}